// round 1
// baseline (speedup 1.0000x reference)
#include <cuda_runtime.h>
#include <cuda_bf16.h>
#include <float.h>
#include <math.h>
#include <stdint.h>

// ---------------- problem constants ----------------
constexpr int   Bn   = 16;
constexpr int   Nn   = 33600;
constexpr int   Cc   = 80;
constexpr int   MAXN = 100;
constexpr float THR  = 0.05f;
constexpr float IOUT = 0.65f;

// ---------------- device scratch (no allocations allowed) ----------------
__device__ float g_scores[Bn * Nn];   // masked score: s if s>=THR else -FLT_MAX
__device__ int   g_labels[Bn * Nn];   // argmax class
__device__ int   g_sel[Bn * MAXN];    // selected anchor indices, in rank order

// ---------------- kernel 1: sigmoid + max/argmax + score ----------------
// 4 lanes per anchor; each lane reads 20 floats (5x float4), contiguous.
__global__ void k_score(const float* __restrict__ cls,
                        const float* __restrict__ obj) {
    int t   = blockIdx.x * blockDim.x + threadIdx.x;
    int a   = t >> 2;          // global anchor index in [0, B*N)
    int sub = t & 3;
    if (a >= Bn * Nn) return;

    const float4* p = reinterpret_cast<const float4*>(cls + (size_t)a * Cc + sub * 20);
    float mx = -FLT_MAX;
    int   mi = 0;
#pragma unroll
    for (int i = 0; i < 5; i++) {
        float4 v = p[i];
        int base = sub * 20 + i * 4;
        if (v.x > mx) { mx = v.x; mi = base; }
        if (v.y > mx) { mx = v.y; mi = base + 1; }
        if (v.z > mx) { mx = v.z; mi = base + 2; }
        if (v.w > mx) { mx = v.w; mi = base + 3; }
    }
    // all-reduce across the 4 lanes of this anchor (butterfly, tie -> smaller idx)
#pragma unroll
    for (int off = 1; off < 4; off <<= 1) {
        float om  = __shfl_xor_sync(0xffffffffu, mx, off);
        int   omi = __shfl_xor_sync(0xffffffffu, mi, off);
        if (om > mx || (om == mx && omi < mi)) { mx = om; mi = omi; }
    }
    if (sub == 0) {
        float o = obj[a];
        float s = (1.0f / (1.0f + __expf(-mx))) * (1.0f / (1.0f + __expf(-o)));
        g_scores[a] = (s >= THR) ? s : -FLT_MAX;
        g_labels[a] = mi;
    }
}

// ---------------- kernel 2: per-batch top-100 (tournament select) ----------------
constexpr int SELT = 1024;                 // threads
constexpr int CH   = (Nn + SELT - 1) / SELT;  // 33 elements per thread chunk
// dynamic smem: sc[Nn] | wv[32] | wi[32] | sels[MAXN] | cur[1]
constexpr int SEL_SMEM = (Nn + 32) * 4 + (32 + MAXN + 1) * 4;

__global__ void k_select() {
    extern __shared__ unsigned char sraw[];
    float* sc   = (float*)sraw;
    float* wv   = sc + Nn;
    int*   wi   = (int*)(wv + 32);
    int*   sels = wi + 32;
    int*   curp = sels + MAXN;

    int b   = blockIdx.x;
    int tid = threadIdx.x;
    const float* src = g_scores + (size_t)b * Nn;

    for (int i = tid; i < Nn; i += SELT) sc[i] = src[i];
    __syncthreads();

    int start = tid * CH;
    int end   = min(start + CH, Nn);
    float cm = -INFINITY;
    int   ci = 0x7fffffff;
    for (int i = start; i < end; i++) {
        float v = sc[i];
        if (v > cm) { cm = v; ci = i; }
    }

    int wid = tid >> 5, lane = tid & 31;

    for (int k = 0; k < MAXN; k++) {
        float m = cm; int mi = ci;
#pragma unroll
        for (int off = 16; off; off >>= 1) {
            float om  = __shfl_xor_sync(0xffffffffu, m, off);
            int   omi = __shfl_xor_sync(0xffffffffu, mi, off);
            if (om > m || (om == m && omi < mi)) { m = om; mi = omi; }
        }
        if (lane == 0) { wv[wid] = m; wi[wid] = mi; }
        __syncthreads();
        if (wid == 0) {
            float m2 = wv[lane]; int mi2 = wi[lane];
#pragma unroll
            for (int off = 16; off; off >>= 1) {
                float om  = __shfl_xor_sync(0xffffffffu, m2, off);
                int   omi = __shfl_xor_sync(0xffffffffu, mi2, off);
                if (om > m2 || (om == m2 && omi < mi2)) { m2 = om; mi2 = omi; }
            }
            if (lane == 0) { curp[0] = mi2; sels[k] = mi2; }
        }
        __syncthreads();
        int w = curp[0];
        if ((unsigned)(w - start) < (unsigned)CH) {   // owner chunk
            sc[w] = -INFINITY;                        // remove (strictly below -FLT_MAX mask)
            cm = -INFINITY; ci = 0x7fffffff;
            for (int i = start; i < end; i++) {
                float v = sc[i];
                if (v > cm) { cm = v; ci = i; }
            }
        }
    }
    if (tid < MAXN) g_sel[b * MAXN + tid] = sels[tid];
}

// ---------------- kernel 3: decode + class-aware greedy NMS + write ----------------
__global__ void k_nms(const float* __restrict__ bbox,
                      const float* __restrict__ priors,
                      float* __restrict__ out,
                      int write_keep) {
    int b   = blockIdx.x;
    int tid = threadIdx.x;

    __shared__ float bx[MAXN][4];
    __shared__ float ar[MAXN];
    __shared__ float ss[MAXN];
    __shared__ int   ll[MAXN];
    __shared__ int   kp[MAXN];

    if (tid < MAXN) {
        int   idx = g_sel[b * MAXN + tid];
        float s   = g_scores[(size_t)b * Nn + idx];
        float4 pr = reinterpret_cast<const float4*>(priors)[idx];
        float4 bp = reinterpret_cast<const float4*>(bbox)[(size_t)b * Nn + idx];
        float cx = bp.x * pr.z + pr.x;
        float cy = bp.y * pr.w + pr.y;
        float w  = __expf(bp.z) * pr.z;
        float h  = __expf(bp.w) * pr.w;
        bx[tid][0] = cx - 0.5f * w;
        bx[tid][1] = cy - 0.5f * h;
        bx[tid][2] = cx + 0.5f * w;
        bx[tid][3] = cy + 0.5f * h;
        ar[tid] = w * h;
        ss[tid] = s;
        ll[tid] = g_labels[(size_t)b * Nn + idx];
        kp[tid] = (s >= THR) ? 1 : 0;   // masked score -FLT_MAX => invalid
    }
    __syncthreads();

    float x1 = 0, y1 = 0, x2 = 0, y2 = 0, aj = 0;
    int lj = -1;
    if (tid < MAXN) {
        x1 = bx[tid][0]; y1 = bx[tid][1]; x2 = bx[tid][2]; y2 = bx[tid][3];
        aj = ar[tid]; lj = ll[tid];
    }

    for (int i = 0; i < MAXN - 1; i++) {
        if (tid < MAXN && tid > i && kp[i] && lj == ll[i]) {
            float ix1 = fmaxf(x1, bx[i][0]);
            float iy1 = fmaxf(y1, bx[i][1]);
            float ix2 = fminf(x2, bx[i][2]);
            float iy2 = fminf(y2, bx[i][3]);
            float inter = fmaxf(ix2 - ix1, 0.0f) * fmaxf(iy2 - iy1, 0.0f);
            float uni   = aj + ar[i] - inter;
            if (inter / (uni + 1e-8f) >= IOUT) kp[tid] = 0;
        }
        __syncthreads();
    }

    if (tid < MAXN) {
        float* row = out + ((size_t)b * MAXN + tid) * 6;
        if (kp[tid]) {
            row[0] = x1; row[1] = y1; row[2] = x2; row[3] = y2;
            row[4] = ss[tid]; row[5] = (float)lj;
        } else {
            row[0] = 0.0f; row[1] = 0.0f; row[2] = 0.0f; row[3] = 0.0f;
            row[4] = 0.0f; row[5] = -1.0f;
        }
        if (write_keep)
            out[(size_t)Bn * MAXN * 6 + b * MAXN + tid] = kp[tid] ? 1.0f : 0.0f;
    }
}

// ---------------- host launcher ----------------
extern "C" void kernel_launch(void* const* d_in, const int* in_sizes, int n_in,
                              void* d_out, int out_size) {
    // Map inputs by element count for robustness.
    const float* cls    = nullptr;  // B*N*C = 43,008,000
    const float* bbox   = nullptr;  // B*N*4 =  2,150,400
    const float* obj    = nullptr;  // B*N   =    537,600
    const float* priors = nullptr;  // N*4   =    134,400
    for (int i = 0; i < n_in; i++) {
        int sz = in_sizes[i];
        if      (sz == Bn * Nn * Cc) cls    = (const float*)d_in[i];
        else if (sz == Bn * Nn * 4)  bbox   = (const float*)d_in[i];
        else if (sz == Bn * Nn)      obj    = (const float*)d_in[i];
        else if (sz == Nn * 4)       priors = (const float*)d_in[i];
    }
    float* out = (float*)d_out;
    int write_keep = (out_size >= Bn * MAXN * 6 + Bn * MAXN) ? 1 : 0;

    cudaFuncSetAttribute(k_select, cudaFuncAttributeMaxDynamicSharedMemorySize, SEL_SMEM);

    int total_threads = Bn * Nn * 4;
    k_score<<<(total_threads + 255) / 256, 256>>>(cls, obj);
    k_select<<<Bn, SELT, SEL_SMEM>>>();
    k_nms<<<Bn, 128>>>(bbox, priors, out, write_keep);
}

// round 2
// speedup vs baseline: 2.0673x; 2.0673x over previous
#include <cuda_runtime.h>
#include <cuda_bf16.h>
#include <float.h>
#include <math.h>
#include <stdint.h>

// ---------------- problem constants ----------------
constexpr int   Bn   = 16;
constexpr int   Nn   = 33600;
constexpr int   Cc   = 80;
constexpr int   MAXN = 100;
constexpr float THR  = 0.05f;
constexpr float IOUT = 0.65f;

// histogram select constants
constexpr unsigned BASE   = 0x3D000000u;           // below bits(0.05)=0x3D4CCCCD
constexpr int      CHUNKB = 11;                     // buckets per thread chunk
constexpr int      NCH    = 1024;                   // chunks (= threads)
constexpr int      NB     = CHUNKB * NCH;           // 11264 buckets (covers < 1.0)
constexpr int      CAP    = 1024;                   // candidate capacity (pow2)

// dynamic smem layout: hist[NB] | csum[NCH] | cand[CAP] | misc[4]
constexpr int SEL_SMEM = NB * 4 + NCH * 4 + CAP * 8 + 4 * 4;

// ---------------- device scratch ----------------
__device__ float g_scores[Bn * Nn];   // masked score: s if s>=THR else -FLT_MAX
__device__ int   g_labels[Bn * Nn];   // argmax class

// ---------------- kernel 1: sigmoid + max/argmax + score ----------------
__global__ void k_score(const float* __restrict__ cls,
                        const float* __restrict__ obj) {
    int t   = blockIdx.x * blockDim.x + threadIdx.x;
    int a   = t >> 2;
    int sub = t & 3;
    if (a >= Bn * Nn) return;

    const float4* p = reinterpret_cast<const float4*>(cls + (size_t)a * Cc + sub * 20);
    float mx = -FLT_MAX;
    int   mi = 0;
#pragma unroll
    for (int i = 0; i < 5; i++) {
        float4 v = p[i];
        int base = sub * 20 + i * 4;
        if (v.x > mx) { mx = v.x; mi = base; }
        if (v.y > mx) { mx = v.y; mi = base + 1; }
        if (v.z > mx) { mx = v.z; mi = base + 2; }
        if (v.w > mx) { mx = v.w; mi = base + 3; }
    }
#pragma unroll
    for (int off = 1; off < 4; off <<= 1) {
        float om  = __shfl_xor_sync(0xffffffffu, mx, off);
        int   omi = __shfl_xor_sync(0xffffffffu, mi, off);
        if (om > mx || (om == mx && omi < mi)) { mx = om; mi = omi; }
    }
    if (sub == 0) {
        float o = obj[a];
        float s = (1.0f / (1.0f + __expf(-mx))) * (1.0f / (1.0f + __expf(-o)));
        g_scores[a] = (s >= THR) ? s : -FLT_MAX;
        g_labels[a] = mi;
    }
}

// ---------------- kernel 2: fused radix-select top-100 + decode + NMS ----------------
__global__ void k_select_nms(const float* __restrict__ bbox,
                             const float* __restrict__ priors,
                             float* __restrict__ out,
                             int write_keep) {
    extern __shared__ unsigned char sraw[];
    unsigned*           hist = (unsigned*)sraw;                 // [NB]
    unsigned*           csum = hist + NB;                       // [NCH]
    unsigned long long* cand = (unsigned long long*)(csum + NCH); // [CAP]
    int*                misc = (int*)(cand + CAP);              // [4]
    // NMS arrays alias the hist region (only used after the sort)
    float* bx = (float*)hist;            // [MAXN*4]
    float* ar = bx + MAXN * 4;           // [MAXN]
    float* ss = ar + MAXN;               // [MAXN]
    int*   ll = (int*)(ss + MAXN);       // [MAXN]
    int*   kp = ll + MAXN;               // [MAXN]

    int b   = blockIdx.x;
    int tid = threadIdx.x;
    const float* sc = g_scores + (size_t)b * Nn;

    // --- pass A: zero histogram ---
#pragma unroll
    for (int i = 0; i < CHUNKB; i++) hist[tid + i * NCH] = 0;
    if (tid < 4) misc[tid] = 0;
    __syncthreads();

    // --- pass B: histogram score bit-patterns ---
    for (int i = tid; i < Nn; i += 1024) {
        float s = sc[i];
        if (s >= THR) {
            unsigned bits = __float_as_uint(s);
            atomicAdd(&hist[(bits - BASE) >> 12], 1u);
        }
    }
    __syncthreads();

    // --- pass C: chunk sums + top-down threshold search ---
    {
        unsigned cs = 0;
#pragma unroll
        for (int i = 0; i < CHUNKB; i++) cs += hist[tid * CHUNKB + i];
        csum[tid] = cs;
    }
    __syncthreads();
    if (tid == 0) {
        int cum = 0;
        int c = NCH - 1;
        for (; c >= 0; c--) {
            int t2 = cum + (int)csum[c];
            if (t2 >= MAXN) break;
            cum = t2;
        }
        int Bb = 0;
        if (c >= 0) {
            int bstart = c * CHUNKB;
            int bb = bstart + CHUNKB - 1;
            for (; bb >= bstart; bb--) {
                int t2 = cum + (int)hist[bb];
                if (t2 >= MAXN) break;
                cum = t2;
            }
            Bb = (bb < bstart) ? bstart : bb;
        }
        misc[0] = Bb;
        misc[1] = 0;   // candidate counter
    }
    __syncthreads();

    // --- pass D: compact candidates >= bucket boundary ---
    unsigned TB = BASE + ((unsigned)misc[0] << 12);
    for (int i = tid; i < Nn; i += 1024) {
        float s = sc[i];
        if (s >= THR) {
            unsigned bits = __float_as_uint(s);
            if (bits >= TB) {
                int pos = atomicAdd(&misc[1], 1);
                if (pos < CAP)
                    cand[pos] = ((unsigned long long)bits << 32) | (unsigned)(~i);
            }
        }
    }
    __syncthreads();
    int cnt = misc[1]; if (cnt > CAP) cnt = CAP;
    if (tid >= cnt) cand[tid] = 0ull;   // sentinel: score bits 0
    __syncthreads();

    // --- pass E: bitonic sort CAP keys, descending ---
    for (unsigned k = 2; k <= (unsigned)CAP; k <<= 1) {
        for (unsigned j = k >> 1; j > 0; j >>= 1) {
            unsigned i = tid, ixj = i ^ j;
            if (ixj > i) {
                unsigned long long a = cand[i], v = cand[ixj];
                bool dirDesc = ((i & k) == 0);
                bool sw = dirDesc ? (a < v) : (a > v);
                if (sw) { cand[i] = v; cand[ixj] = a; }
            }
            __syncthreads();
        }
    }

    // --- pass F: decode top-100 + NMS (threads < 128, named barrier) ---
    if (tid >= 128) return;

    float x1 = 0, y1 = 0, x2 = 0, y2 = 0, aj = 0, sj = 0;
    int lj = -1;
    if (tid < MAXN) {
        unsigned long long key = cand[tid];
        unsigned bits = (unsigned)(key >> 32);
        int valid = (bits != 0u);
        int idx   = valid ? (int)(~(unsigned)(key & 0xffffffffu)) : 0;
        sj = __uint_as_float(bits);
        float4 pr = reinterpret_cast<const float4*>(priors)[idx];
        float4 bp = reinterpret_cast<const float4*>(bbox)[(size_t)b * Nn + idx];
        float cx = bp.x * pr.z + pr.x;
        float cy = bp.y * pr.w + pr.y;
        float w  = __expf(bp.z) * pr.z;
        float h  = __expf(bp.w) * pr.w;
        x1 = cx - 0.5f * w; y1 = cy - 0.5f * h;
        x2 = cx + 0.5f * w; y2 = cy + 0.5f * h;
        aj = w * h;
        lj = g_labels[(size_t)b * Nn + idx];
        bx[tid * 4 + 0] = x1; bx[tid * 4 + 1] = y1;
        bx[tid * 4 + 2] = x2; bx[tid * 4 + 3] = y2;
        ar[tid] = aj; ss[tid] = sj; ll[tid] = lj;
        kp[tid] = valid;
    }
    asm volatile("bar.sync 1, 128;" ::: "memory");

    for (int i = 0; i < MAXN - 1; i++) {
        if (tid < MAXN && tid > i && kp[i] && lj == ll[i]) {
            float ix1 = fmaxf(x1, bx[i * 4 + 0]);
            float iy1 = fmaxf(y1, bx[i * 4 + 1]);
            float ix2 = fminf(x2, bx[i * 4 + 2]);
            float iy2 = fminf(y2, bx[i * 4 + 3]);
            float inter = fmaxf(ix2 - ix1, 0.0f) * fmaxf(iy2 - iy1, 0.0f);
            float uni   = aj + ar[i] - inter;
            if (inter / (uni + 1e-8f) >= IOUT) kp[tid] = 0;
        }
        asm volatile("bar.sync 1, 128;" ::: "memory");
    }

    if (tid < MAXN) {
        float* row = out + ((size_t)b * MAXN + tid) * 6;
        if (kp[tid]) {
            row[0] = x1; row[1] = y1; row[2] = x2; row[3] = y2;
            row[4] = sj; row[5] = (float)lj;
        } else {
            row[0] = 0.0f; row[1] = 0.0f; row[2] = 0.0f; row[3] = 0.0f;
            row[4] = 0.0f; row[5] = -1.0f;
        }
        if (write_keep)
            out[(size_t)Bn * MAXN * 6 + b * MAXN + tid] = kp[tid] ? 1.0f : 0.0f;
    }
}

// ---------------- host launcher ----------------
extern "C" void kernel_launch(void* const* d_in, const int* in_sizes, int n_in,
                              void* d_out, int out_size) {
    const float* cls    = nullptr;
    const float* bbox   = nullptr;
    const float* obj    = nullptr;
    const float* priors = nullptr;
    for (int i = 0; i < n_in; i++) {
        int sz = in_sizes[i];
        if      (sz == Bn * Nn * Cc) cls    = (const float*)d_in[i];
        else if (sz == Bn * Nn * 4)  bbox   = (const float*)d_in[i];
        else if (sz == Bn * Nn)      obj    = (const float*)d_in[i];
        else if (sz == Nn * 4)       priors = (const float*)d_in[i];
    }
    float* out = (float*)d_out;
    int write_keep = (out_size >= Bn * MAXN * 6 + Bn * MAXN) ? 1 : 0;

    static int attr_set = 0;
    cudaFuncSetAttribute(k_select_nms, cudaFuncAttributeMaxDynamicSharedMemorySize, SEL_SMEM);
    (void)attr_set;

    int total_threads = Bn * Nn * 4;
    k_score<<<(total_threads + 255) / 256, 256>>>(cls, obj);
    k_select_nms<<<Bn, 1024, SEL_SMEM>>>(bbox, priors, out, write_keep);
}